// round 5
// baseline (speedup 1.0000x reference)
#include <cuda_runtime.h>
#include <cooperative_groups.h>
namespace cg = cooperative_groups;

#define BATCH 64
#define NPTS  8192
#define SGRID 384
#define OUTD  128
// Fused kernel: 1024 blocks (16 per batch) x 256 threads, 2 points/thread.
#define GRID_BLKS   1024
#define FUSED_THRS  (GRID_BLKS * 256)       // 262144
// Scratch: 16B-padded cells, 64*128*128*4 floats = 16 MB
#define CELLS       (BATCH * OUTD * OUTD)   // 1,048,576
#define SCRATCH_F4  CELLS                   // one float4 per cell

__device__ float d_scratch[CELLS * 4];      // static scratch (no allocs allowed)
__device__ int2  d_blockmin[GRID_BLKS];     // per-block coord minima

// Single 16B vector reduction — sm_90+; address must be 16B aligned.
__device__ __forceinline__ void red_add_v4f32(float* p, float a, float b, float c) {
    asm volatile("red.global.add.v4.f32 [%0], {%1, %2, %3, %4};"
                 :: "l"(p), "f"(a), "f"(b), "f"(c), "f"(0.0f) : "memory");
}

// ---------------------------------------------------------------------------
// Fused kernel: zero scratch + lattice math + per-batch min (grid.sync) +
// one v4 reduction per point into padded scratch.
// ---------------------------------------------------------------------------
__global__ void __launch_bounds__(256, 7)
k_fused(const float* __restrict__ pc1,
        const float* __restrict__ feat,
        const float* __restrict__ tmat)
{
    const int b    = blockIdx.x >> 4;               // 16 blocks per batch
    const int base = (blockIdx.x & 15) << 9;        // 512 points per block

    // ---- zero scratch: 1,048,576 float4 over 262,144 threads (4 each) ----
    {
        const int gid = blockIdx.x * 256 + threadIdx.x;
        const float4 z = make_float4(0.f, 0.f, 0.f, 0.f);
        float4* s4 = reinterpret_cast<float4*>(d_scratch);
        #pragma unroll
        for (int i = 0; i < 4; i++) s4[(size_t)i * FUSED_THRS + gid] = z;
    }

    __shared__ float M[9];
    if (threadIdx.x < 9) M[threadIdx.x] = tmat[b * 9 + threadIdx.x];
    __syncthreads();

    unsigned pk[2];
    int mm0 = 0x7FFFFFFF, mm1 = 0x7FFFFFFF;

    #pragma unroll
    for (int k = 0; k < 2; k++) {
        const int n = base + threadIdx.x + (k << 8);
        const float* p = pc1 + (size_t)b * 3 * NPTS + n;
        const float p0 = p[0], p1 = p[NPTS], p2 = p[2 * NPTS];

        const float e0 = M[0] * p0 + M[1] * p1 + M[2] * p2;
        const float e1 = M[3] * p0 + M[4] * p1 + M[5] * p2;
        const float e2 = M[6] * p0 + M[7] * p1 + M[8] * p2;

        // greedy = round(e/3)*3 (IEEE div + round-half-even, matching jnp)
        const float q0 = rintf(__fdiv_rn(e0, 3.0f));
        const float q1 = rintf(__fdiv_rn(e1, 3.0f));
        const float q2 = rintf(__fdiv_rn(e2, 3.0f));
        const float d0 = e0 - 3.0f * q0;
        const float d1 = e1 - 3.0f * q1;
        const float d2 = e2 - 3.0f * q2;

        const int i0 = (int)q0, i1 = (int)q1, i2 = (int)q2;
        const int rs = i0 + i1 + i2;                 // remainder_sum (exact)

        // rank = inverse of stable descending argsort of (d0,d1,d2)
        int rk0 = (d1 > d0) + (d2 > d0);
        int rk1 = (d0 > d1) + (d2 > d1) + (d0 == d1);

        int g0 = 3 * i0;
        int g1 = 3 * i1;

        int sh0 = 0, sh1 = 0;
        if (rs > 0) {
            const int thr = 3 - rs;
            sh0 = (rk0 >= thr) ? -3 : 0;
            sh1 = (rk1 >= thr) ? -3 : 0;
        } else if (rs < 0) {
            sh0 = (rk0 < -rs) ? 3 : 0;
            sh1 = (rk1 < -rs) ? 3 : 0;
        }
        g0 += sh0;  g1 += sh1;
        rk0 += sh0 + rs;
        rk1 += sh1 + rs;

        // JAX gather semantics for CANONICAL[rank]: wrap negatives +3, clamp [0,2]
        int cr0 = (rk0 < 0) ? rk0 + 3 : rk0;  cr0 = min(max(cr0, 0), 2);
        int cr1 = (rk1 < 0) ? rk1 + 3 : rk1;  cr1 = min(max(cr1, 0), 2);

        mm0 = min(mm0, g0 - cr0);   // min_r CANONICAL[cr][r] == -cr
        mm1 = min(mm1, g1 - cr1);

        pk[k] = (unsigned)(g0 + 1024) | ((unsigned)(g1 + 1024) << 16);
    }

    // ---- block min-reduction -> one int2 store ----
    {
        int m0 = mm0, m1 = mm1;
        #pragma unroll
        for (int o = 16; o; o >>= 1) {
            m0 = min(m0, __shfl_xor_sync(0xFFFFFFFFu, m0, o));
            m1 = min(m1, __shfl_xor_sync(0xFFFFFFFFu, m1, o));
        }
        __shared__ int s0[8], s1[8];
        if ((threadIdx.x & 31) == 0) {
            s0[threadIdx.x >> 5] = m0;
            s1[threadIdx.x >> 5] = m1;
        }
        __syncthreads();
        if (threadIdx.x == 0) {
            int a = s0[0], c = s1[0];
            #pragma unroll
            for (int w = 1; w < 8; w++) { a = min(a, s0[w]); c = min(c, s1[w]); }
            d_blockmin[blockIdx.x] = make_int2(a, c);
        }
    }

    cg::this_grid().sync();   // zero-fill + all block minima globally visible

    // ---- per-batch offset: reduce this batch's 16 block minima ----
    __shared__ int soff0, soff1;
    if (threadIdx.x < 16) {
        int2 v = d_blockmin[(b << 4) + threadIdx.x];
        int a = v.x, c = v.y;
        #pragma unroll
        for (int o = 8; o; o >>= 1) {
            a = min(a, __shfl_xor_sync(0xFFFFu, a, o));
            c = min(c, __shfl_xor_sync(0xFFFFu, c, o));
        }
        if (threadIdx.x == 0) { soff0 = a; soff1 = c; }
    }
    __syncthreads();

    // ---- scatter: one red.v4 per point into padded scratch ----
    #pragma unroll
    for (int k = 0; k < 2; k++) {
        const int n  = base + threadIdx.x + (k << 8);
        const int g0 = (int)(pk[k] & 0xFFFFu) - 1024;
        const int g1 = (int)(pk[k] >> 16)     - 1024;
        const int row = g0 - soff0;       // >= 0 (offset is the min)
        const int col = g1 - soff1;
        if (row < SGRID && col < SGRID) {
            const int u = row / 3;        // row ≡ pts_pick0 (mod 3) exactly
            const int v = col / 3;
            const int idx = (b << 14) + (u << 7) + v;
            const float* f = feat + (size_t)b * 3 * NPTS + n;
            red_add_v4f32(d_scratch + (size_t)idx * 4, f[0], f[NPTS], f[2 * NPTS]);
        }
    }
}

// ---------------------------------------------------------------------------
// Compact: scratch (16B cells) -> out (12B cells), fully coalesced 128-bit.
// Each thread handles 4 cells: 64B in, 48B out (both 16B aligned).
// ---------------------------------------------------------------------------
__global__ void __launch_bounds__(256) k_compact(float* __restrict__ out)
{
    const int j = blockIdx.x * 256 + threadIdx.x;   // 262144 threads, 4 cells each
    const float4* s = reinterpret_cast<const float4*>(d_scratch) + (size_t)j * 4;
    const float4 a = s[0], b = s[1], c = s[2], d = s[3];
    float4* o = reinterpret_cast<float4*>(out) + (size_t)j * 3;
    o[0] = make_float4(a.x, a.y, a.z, b.x);
    o[1] = make_float4(b.y, b.z, c.x, c.y);
    o[2] = make_float4(c.z, d.x, d.y, d.z);
}

// ---------------------------------------------------------------------------
extern "C" void kernel_launch(void* const* d_in, const int* in_sizes, int n_in,
                              void* d_out, int out_size)
{
    const float* pc1  = (const float*)d_in[0];
    const float* feat = (const float*)d_in[1];
    const float* tmat = (const float*)d_in[2];
    float*       out  = (float*)d_out;

    void* args[] = { (void*)&pc1, (void*)&feat, (void*)&tmat };
    cudaLaunchCooperativeKernel((const void*)k_fused,
                                dim3(GRID_BLKS), dim3(256), args, 0, 0);
    k_compact<<<GRID_BLKS, 256>>>(out);
}

// round 6
// speedup vs baseline: 1.1303x; 1.1303x over previous
#include <cuda_runtime.h>
#include <cooperative_groups.h>
namespace cg = cooperative_groups;

#define BATCH 64
#define NPTS  8192
#define SGRID 384
#define OUTD  128
// Single cooperative kernel: 1024 blocks (16 per batch) x 256 threads,
// 2 points per thread. Co-residency: 7 blocks/SM x 148 SMs >= 1024.
#define GRID_BLKS 1024
#define OUT_F4    786432            // 64*128*128*3 floats / 4

__device__ int2 d_blockmin[GRID_BLKS];   // per-block coord minima

// float2 vector reduction (no return) — sm_90+; needs 8B-aligned address.
__device__ __forceinline__ void red_add_v2f32(float* p, float a, float b) {
    asm volatile("red.global.add.v2.f32 [%0], {%1, %2};"
                 :: "l"(p), "f"(a), "f"(b) : "memory");
}

// ---------------------------------------------------------------------------
// Fused: zero out + lattice math + per-block min -> grid.sync ->
// per-batch offset + scatter straight into out (2 reds per point).
// ---------------------------------------------------------------------------
__global__ void __launch_bounds__(256, 7)
k_fused(const float* __restrict__ pc1,
        const float* __restrict__ feat,
        const float* __restrict__ tmat,
        float* __restrict__ out)
{
    const int b    = blockIdx.x >> 4;            // 16 blocks per batch
    const int base = (blockIdx.x & 15) << 9;     // 512 points per block

    // ---- zero-fill out: 786432 float4 over 262144 threads (3 each) ----
    {
        const int gid = blockIdx.x * 256 + threadIdx.x;
        const float4 z = make_float4(0.f, 0.f, 0.f, 0.f);
        float4* o4 = reinterpret_cast<float4*>(out);
        #pragma unroll
        for (int i = 0; i < 3; i++) o4[(size_t)i * (GRID_BLKS * 256) + gid] = z;
    }

    __shared__ float M[9];
    if (threadIdx.x < 9) M[threadIdx.x] = tmat[b * 9 + threadIdx.x];
    __syncthreads();

    unsigned pk[2];
    int mm0 = 0x7FFFFFFF, mm1 = 0x7FFFFFFF;

    #pragma unroll
    for (int k = 0; k < 2; k++) {
        const int n = base + threadIdx.x + (k << 8);
        const float* p = pc1 + (size_t)b * 3 * NPTS + n;
        const float p0 = p[0], p1 = p[NPTS], p2 = p[2 * NPTS];

        const float e0 = M[0] * p0 + M[1] * p1 + M[2] * p2;
        const float e1 = M[3] * p0 + M[4] * p1 + M[5] * p2;
        const float e2 = M[6] * p0 + M[7] * p1 + M[8] * p2;

        // greedy = round(e/3)*3 (IEEE div + round-half-even, matching jnp)
        const float q0 = rintf(__fdiv_rn(e0, 3.0f));
        const float q1 = rintf(__fdiv_rn(e1, 3.0f));
        const float q2 = rintf(__fdiv_rn(e2, 3.0f));
        const float d0 = e0 - 3.0f * q0;
        const float d1 = e1 - 3.0f * q1;
        const float d2 = e2 - 3.0f * q2;

        const int i0 = (int)q0, i1 = (int)q1, i2 = (int)q2;
        const int rs = i0 + i1 + i2;             // remainder_sum (exact)

        // rank = inverse of stable descending argsort of (d0,d1,d2)
        int rk0 = (d1 > d0) + (d2 > d0);
        int rk1 = (d0 > d1) + (d2 > d1) + (d0 == d1);

        int g0 = 3 * i0;
        int g1 = 3 * i1;

        int sh0 = 0, sh1 = 0;
        if (rs > 0) {
            const int thr = 3 - rs;
            sh0 = (rk0 >= thr) ? -3 : 0;
            sh1 = (rk1 >= thr) ? -3 : 0;
        } else if (rs < 0) {
            sh0 = (rk0 < -rs) ? 3 : 0;
            sh1 = (rk1 < -rs) ? 3 : 0;
        }
        g0 += sh0;  g1 += sh1;
        rk0 += sh0 + rs;
        rk1 += sh1 + rs;

        // JAX gather semantics for CANONICAL[rank]: wrap negatives +3, clamp [0,2]
        int cr0 = (rk0 < 0) ? rk0 + 3 : rk0;  cr0 = min(max(cr0, 0), 2);
        int cr1 = (rk1 < 0) ? rk1 + 3 : rk1;  cr1 = min(max(cr1, 0), 2);

        mm0 = min(mm0, g0 - cr0);   // min_r CANONICAL[cr][r] == -cr
        mm1 = min(mm1, g1 - cr1);

        pk[k] = (unsigned)(g0 + 1024) | ((unsigned)(g1 + 1024) << 16);
    }

    // ---- block min-reduction -> one int2 store ----
    {
        int m0 = mm0, m1 = mm1;
        #pragma unroll
        for (int o = 16; o; o >>= 1) {
            m0 = min(m0, __shfl_xor_sync(0xFFFFFFFFu, m0, o));
            m1 = min(m1, __shfl_xor_sync(0xFFFFFFFFu, m1, o));
        }
        __shared__ int s0[8], s1[8];
        if ((threadIdx.x & 31) == 0) {
            s0[threadIdx.x >> 5] = m0;
            s1[threadIdx.x >> 5] = m1;
        }
        __syncthreads();
        if (threadIdx.x == 0) {
            int a = s0[0], c = s1[0];
            #pragma unroll
            for (int w = 1; w < 8; w++) { a = min(a, s0[w]); c = min(c, s1[w]); }
            d_blockmin[blockIdx.x] = make_int2(a, c);
        }
    }

    cg::this_grid().sync();   // zero-fill + block minima globally visible

    // ---- per-batch offset: reduce this batch's 16 block minima ----
    __shared__ int soff0, soff1;
    if (threadIdx.x < 16) {
        int2 v = d_blockmin[(b << 4) + threadIdx.x];
        int a = v.x, c = v.y;
        #pragma unroll
        for (int o = 8; o; o >>= 1) {
            a = min(a, __shfl_xor_sync(0xFFFFu, a, o));
            c = min(c, __shfl_xor_sync(0xFFFFu, c, o));
        }
        if (threadIdx.x == 0) { soff0 = a; soff1 = c; }
    }
    __syncthreads();
    const int off0 = soff0, off1 = soff1;

    // ---- scatter straight into out: red.v2 + scalar red (parity trick) ----
    #pragma unroll
    for (int k = 0; k < 2; k++) {
        const int n  = base + threadIdx.x + (k << 8);
        const int g0 = (int)(pk[k] & 0xFFFFu) - 1024;
        const int g1 = (int)(pk[k] >> 16)     - 1024;
        const int row = g0 - off0;        // >= 0 (offset is the min)
        const int col = g1 - off1;
        if (row < SGRID && col < SGRID) {
            const int u = row / 3;        // row ≡ pts_pick0 (mod 3) exactly
            const int v = col / 3;
            const int idx = (b << 14) + (u << 7) + v;
            float* o = out + (size_t)idx * 3;
            const float* f = feat + (size_t)b * 3 * NPTS + n;
            const float f0 = f[0], f1 = f[NPTS], f2 = f[2 * NPTS];
            // cell byte base = 12*idx: even idx -> &o[0] 8-aligned,
            // odd idx -> &o[1] 8-aligned. Always one v2 + one scalar red.
            const int odd = idx & 1;
            red_add_v2f32(o + odd, odd ? f1 : f0, odd ? f2 : f1);
            atomicAdd(o + (odd ? 0 : 2), odd ? f0 : f2);
        }
    }
}

// ---------------------------------------------------------------------------
extern "C" void kernel_launch(void* const* d_in, const int* in_sizes, int n_in,
                              void* d_out, int out_size)
{
    const float* pc1  = (const float*)d_in[0];
    const float* feat = (const float*)d_in[1];
    const float* tmat = (const float*)d_in[2];
    float*       out  = (float*)d_out;

    void* args[] = { (void*)&pc1, (void*)&feat, (void*)&tmat, (void*)&out };
    cudaLaunchCooperativeKernel((const void*)k_fused,
                                dim3(GRID_BLKS), dim3(256), args, 0, 0);
}